// round 10
// baseline (speedup 1.0000x reference)
#include <cuda_runtime.h>
#include <cuda_bf16.h>
#include <cstdint>

#define DIMK   512
#define NCLS   11003
#define NCPAD  11008
#define NPART  5
#define NSEGC  6
#define NPIX   4096
#define SCALE_C 28.0f

// ---------------- device scratch ----------------
__device__ float g_sumW[NCPAD];           // per-column sum of squares (atomic)
__device__ float g_invW[NCPAD];
__device__ float g_invRow[3072];          // [0,512) v|t, [512,1792) part, [1792,3072) attr
__device__ float g_rowSumExp[512];
__device__ float g_labelLogit[512];
__device__ float g_sim[NPART * 256 * 256];
__device__ int   g_rowTop[NPART * 256 * 8];
__device__ int   g_colTop[NPART * 256 * 8];
__device__ float g_accum[4];              // 0: mask ce, 1: global, 2: local

// bf16 operands (UNNORMALIZED; norms applied in epilogues). W transposed K-major.
__device__ __align__(16) __nv_bfloat16 g_Ahi[512 * DIMK];
__device__ __align__(16) __nv_bfloat16 g_Whi[NCPAD * DIMK];

// ---------------- helpers ----------------
__device__ __forceinline__ uint32_t smem_u32(const void* p) {
    uint32_t a;
    asm("{ .reg .u64 t; cvta.to.shared.u64 t, %1; cvt.u32.u64 %0, t; }" : "=r"(a) : "l"(p));
    return a;
}
#define CP16(dst, src) asm volatile("cp.async.cg.shared.global [%0], [%1], 16;" :: "r"(dst), "l"(src))
#define CP_COMMIT()    asm volatile("cp.async.commit_group;" ::: "memory")

__device__ __forceinline__ void ldm4(uint32_t* r, uint32_t addr) {
    asm volatile("ldmatrix.sync.aligned.m8n8.x4.shared.b16 {%0,%1,%2,%3}, [%4];"
                 : "=r"(r[0]), "=r"(r[1]), "=r"(r[2]), "=r"(r[3]) : "r"(addr));
}
__device__ __forceinline__ void mma16816(float* c, const uint32_t* a, uint32_t b0, uint32_t b1) {
    asm volatile("mma.sync.aligned.m16n8k16.row.col.f32.bf16.bf16.f32 "
                 "{%0,%1,%2,%3}, {%4,%5,%6,%7}, {%8,%9}, {%0,%1,%2,%3};"
                 : "+f"(c[0]), "+f"(c[1]), "+f"(c[2]), "+f"(c[3])
                 : "r"(a[0]), "r"(a[1]), "r"(a[2]), "r"(a[3]), "r"(b0), "r"(b1));
}

__device__ __forceinline__ float softplusf(float x) {
    return x > 15.f ? x : log1pf(__expf(x));
}
__device__ __forceinline__ float blockReduceSum(float v, float* sh) {
    int t = threadIdx.x;
    #pragma unroll
    for (int o = 16; o; o >>= 1) v += __shfl_xor_sync(0xffffffffu, v, o);
    if ((t & 31) == 0) sh[t >> 5] = v;
    __syncthreads();
    int nw = (blockDim.x + 31) >> 5;
    if (t < 32) {
        v = (t < nw) ? sh[t] : 0.f;
        #pragma unroll
        for (int o = 16; o; o >>= 1) v += __shfl_xor_sync(0xffffffffu, v, o);
    }
    return v;
}

// ================= init0: zero accumulators (before stream fork) =================
__global__ void k_init0() {
    int t = blockIdx.x * 256 + threadIdx.x;
    if (t < NCPAD) g_sumW[t] = 0.f;
    if (t < 512) { g_rowSumExp[t] = 0.f; g_labelLogit[t] = 0.f; }
    if (t < 4) g_accum[t] = 0.f;
}

// ================= pre1: row norms only =================
#define NB_ROWNORM 384
__global__ __launch_bounds__(256) void k_pre1(
    const float* __restrict__ vis, const float* __restrict__ txt,
    const float* __restrict__ pe, const float* __restrict__ ae) {
    int warp = blockIdx.x * 8 + (threadIdx.x >> 5);
    int lane = threadIdx.x & 31;
    const float* src;
    if (warp < 256)       src = vis + warp * DIMK;
    else if (warp < 512)  src = txt + (warp - 256) * DIMK;
    else if (warp < 1792) src = pe + (warp - 512) * DIMK;
    else                  src = ae + (warp - 1792) * DIMK;
    float s = 0.f;
    #pragma unroll 4
    for (int j = lane; j < DIMK; j += 32) { float v = src[j]; s = fmaf(v, v, s); }
    #pragma unroll
    for (int o = 16; o; o >>= 1) s += __shfl_xor_sync(0xffffffffu, s, o);
    if (!lane) g_invRow[warp] = rsqrtf(s);
}

// ================= prepAW: bf16 conversion + W colnorm partial sums =================
#define NB_PREPA 128
#define NB_PREPW 5504        /* 344 x 16 */
__global__ __launch_bounds__(256) void k_prepAW(
    const float* __restrict__ vis, const float* __restrict__ txt,
    const float* __restrict__ W) {
    __shared__ float sh[32][33];
    int b = blockIdx.x;
    int tid = threadIdx.x;
    if (b < NB_PREPA) {
        #pragma unroll
        for (int rr = 0; rr < 4; rr++) {
            int row = b * 4 + rr;
            const float* src = (row < 256) ? (vis + row * DIMK) : (txt - 256 * DIMK + row * DIMK);
            for (int j = tid; j < DIMK; j += 256)
                g_Ahi[row * DIMK + j] = __float2bfloat16(src[j]);
        }
    } else {
        int w = b - NB_PREPA;
        int c0 = (w % 344) * 32;
        int d0 = (w / 344) * 32;
        int tx = tid & 31;   // lane
        int ty = tid >> 5;   // warp 0..7
        #pragma unroll
        for (int j = 0; j < 4; j++) {
            int d = d0 + ty + j * 8;
            int c = c0 + tx;
            sh[ty + j * 8][tx] = (c < NCLS) ? W[d * NCLS + c] : 0.f;
        }
        __syncthreads();
        // transpose-write bf16 + per-column sumsq partials
        #pragma unroll
        for (int j = 0; j < 4; j++) {
            int cl = ty + j * 8;           // column-local 0..31
            float x = sh[tx][cl];          // d_local = tx (=lane), col = cl
            g_Whi[(c0 + cl) * DIMK + d0 + tx] = __float2bfloat16(x);
            float p = x * x;               // reduce over tx (lanes) = over 32 d's
            #pragma unroll
            for (int o = 16; o; o >>= 1) p += __shfl_xor_sync(0xffffffffu, p, o);
            if (tx == 0) atomicAdd(&g_sumW[c0 + cl], p);
        }
    }
}

// ================= rsqrtW: finalize column inverse norms =================
__global__ void k_rsqrtW() {
    int c = blockIdx.x * 256 + threadIdx.x;
    if (c < NCPAD) g_invW[c] = rsqrtf(g_sumW[c]);
}

// ================= mma: bf16 A x bf16 W, norm+CE epilogue =================
#define ROWB     80
#define A_BYTES  (128 * ROWB)             // 10240
#define B_BYTES  (64 * ROWB)              // 5120
#define BUF_BYTES (A_BYTES + B_BYTES)     // 15360
#define OFF_AHI  0
#define OFF_BHI  A_BYTES
#define SM_TOTAL (2 * BUF_BYTES)          // 30720
#define NB_MMA   688                      /* 172 col tiles x 4 row tiles */

__global__ __launch_bounds__(256, 2) void k_mma(const int* __restrict__ labels) {
    extern __shared__ char smem[];
    const int tid = threadIdx.x;
    const int wid = tid >> 5, lane = tid & 31;
    // col-tile-major ordering: 4 row blocks sharing a W tile adjacent -> L2 reuse
    const int row0 = (blockIdx.x & 3) * 128;
    const int col0 = (blockIdx.x >> 2) * 64;
    const int warpM = wid & 3;
    const int warpN = wid >> 2;
    const uint32_t sbase = smem_u32(smem);

    float acc[2][4][4];
    #pragma unroll
    for (int i = 0; i < 2; i++)
        #pragma unroll
        for (int j = 0; j < 4; j++)
            #pragma unroll
            for (int k = 0; k < 4; k++) acc[i][j][k] = 0.f;

    auto load_chunk = [&](int kc, int buf) {
        uint32_t bb = sbase + buf * BUF_BYTES;
        {
            int r = tid >> 1, h = tid & 1;
            long off = (long)(row0 + r) * DIMK + kc * 32 + h * 16;
            uint32_t d = bb + OFF_AHI + r * ROWB + h * 32;
            CP16(d,      g_Ahi + off);
            CP16(d + 16, g_Ahi + off + 8);
        }
        if (tid < 128) {
            int r = tid >> 1, h = tid & 1;
            long off = (long)(col0 + r) * DIMK + kc * 32 + h * 16;
            uint32_t d = bb + OFF_BHI + r * ROWB + h * 32;
            CP16(d,      g_Whi + off);
            CP16(d + 16, g_Whi + off + 8);
        }
    };

    load_chunk(0, 0);
    CP_COMMIT();

    for (int kc = 0; kc < 16; kc++) {
        int buf = kc & 1;
        if (kc < 15) {
            load_chunk(kc + 1, buf ^ 1);
            CP_COMMIT();
            asm volatile("cp.async.wait_group 1;" ::: "memory");
        } else {
            asm volatile("cp.async.wait_group 0;" ::: "memory");
        }
        __syncthreads();

        uint32_t bb = sbase + buf * BUF_BYTES;
        #pragma unroll
        for (int ks = 0; ks < 2; ks++) {
            uint32_t ah[2][4], bh[2][4];
            #pragma unroll
            for (int mi = 0; mi < 2; mi++) {
                uint32_t ra = (uint32_t)((warpM * 32 + mi * 16 + (lane & 15)) * ROWB +
                                         (ks * 2 + (lane >> 4)) * 16);
                ldm4(ah[mi], bb + OFF_AHI + ra);
            }
            #pragma unroll
            for (int j = 0; j < 2; j++) {
                uint32_t rb = (uint32_t)((warpN * 32 + j * 16 + ((lane >> 4) << 3) + (lane & 7)) * ROWB +
                                         (ks * 2 + ((lane >> 3) & 1)) * 16);
                ldm4(bh[j], bb + OFF_BHI + rb);
            }
            #pragma unroll
            for (int mi = 0; mi < 2; mi++) {
                #pragma unroll
                for (int ni = 0; ni < 4; ni++) {
                    int j = ni >> 1, loc = ni & 1;
                    mma16816(acc[mi][ni], ah[mi], bh[j][loc * 2], bh[j][loc * 2 + 1]);
                }
            }
        }
        __syncthreads();
    }

    // epilogue: apply norms, shifted sumexp + label capture
    int q = lane >> 2, qc = lane & 3;
    #pragma unroll
    for (int mi = 0; mi < 2; mi++) {
        #pragma unroll
        for (int half = 0; half < 2; half++) {
            int row = row0 + warpM * 32 + mi * 16 + half * 8 + q;
            float invA = SCALE_C * g_invRow[row];
            int lbl = labels[row & 255];
            float rs = 0.f;
            #pragma unroll
            for (int ni = 0; ni < 4; ni++) {
                #pragma unroll
                for (int j = 0; j < 2; j++) {
                    int c = col0 + warpN * 32 + ni * 8 + qc * 2 + j;
                    if (c < NCLS) {
                        float lg = acc[mi][ni][half * 2 + j] * invA * g_invW[c];
                        rs += __expf(lg - SCALE_C);
                        if (c == lbl) g_labelLogit[row] = lg;
                    }
                }
            }
            rs += __shfl_xor_sync(0xffffffffu, rs, 1);
            rs += __shfl_xor_sync(0xffffffffu, rs, 2);
            if (qc == 0) atomicAdd(&g_rowSumExp[row], rs);
        }
    }
}

// ================= mask loss (standalone, parallel stream) =================
__global__ __launch_bounds__(256) void k_mask(const float* __restrict__ seg,
                                              const int* __restrict__ masks) {
    __shared__ float sred[8];
    int n = blockIdx.x;
    int tid = threadIdx.x;
    const float4* base4 = (const float4*)(seg + (long long)n * NSEGC * NPIX);
    const int4* mb4 = (const int4*)(masks + n * NPIX);
    float lsum = 0.f;
    auto ce = [&](float a0, float a1, float a2, float a3, float a4, float a5, int k) {
        float m = fmaxf(fmaxf(fmaxf(a0, a1), fmaxf(a2, a3)), fmaxf(a4, a5));
        float s = __expf(a0 - m) + __expf(a1 - m) + __expf(a2 - m) +
                  __expf(a3 - m) + __expf(a4 - m) + __expf(a5 - m);
        float pk = k == 0 ? a0 : k == 1 ? a1 : k == 2 ? a2 : k == 3 ? a3 : k == 4 ? a4 : a5;
        lsum += m + __logf(s) - pk;
    };
    #pragma unroll
    for (int it = 0; it < 4; it++) {
        int pidx = tid + it * 256;
        float4 x[NSEGC];
        #pragma unroll
        for (int ch = 0; ch < NSEGC; ch++) x[ch] = base4[ch * 1024 + pidx];
        int4 kk = mb4[pidx];
        ce(x[0].x, x[1].x, x[2].x, x[3].x, x[4].x, x[5].x, kk.x);
        ce(x[0].y, x[1].y, x[2].y, x[3].y, x[4].y, x[5].y, kk.y);
        ce(x[0].z, x[1].z, x[2].z, x[3].z, x[4].z, x[5].z, kk.z);
        ce(x[0].w, x[1].w, x[2].w, x[3].w, x[4].w, x[5].w, kk.w);
    }
    float tot = blockReduceSum(lsum, sred);
    if (tid == 0) atomicAdd(&g_accum[0], tot);
}

// ================= sim GEMMs (z=0 global align fused; z=1..5 to scratch) =================
__global__ __launch_bounds__(256) void k_sim(
    const float* __restrict__ vis, const float* __restrict__ txt,
    const float* __restrict__ pe, const float* __restrict__ ae,
    const int* __restrict__ labels) {
    __shared__ float As[32][68];
    __shared__ float Bs[32][68];
    __shared__ float sred[8];
    int z = blockIdx.z;
    int tid = threadIdx.x;
    int tx = tid & 15, ty = tid >> 4;
    int r0 = blockIdx.y * 64, c0 = blockIdx.x * 64;

    const float* abase; const float* bbase; int aIdx, bIdx;
    if (z == 0) { abase = vis; bbase = txt; aIdx = 0; bIdx = 256; }
    else {
        int p = z - 1;
        abase = pe + p * 256 * DIMK; bbase = ae + p * 256 * DIMK;
        aIdx = 512 + p * 256; bIdx = 1792 + p * 256;
    }

    float acc[4][4];
    #pragma unroll
    for (int i = 0; i < 4; i++)
        #pragma unroll
        for (int j = 0; j < 4; j++) acc[i][j] = 0.f;

    int lm = tid >> 2, lseg = tid & 3;
    for (int kt = 0; kt < DIMK; kt += 32) {
        float4 v0 = *(const float4*)(abase + (r0 + lm) * DIMK + kt + lseg * 8);
        float4 v1 = *(const float4*)(abase + (r0 + lm) * DIMK + kt + lseg * 8 + 4);
        As[lseg * 8 + 0][lm] = v0.x; As[lseg * 8 + 1][lm] = v0.y;
        As[lseg * 8 + 2][lm] = v0.z; As[lseg * 8 + 3][lm] = v0.w;
        As[lseg * 8 + 4][lm] = v1.x; As[lseg * 8 + 5][lm] = v1.y;
        As[lseg * 8 + 6][lm] = v1.z; As[lseg * 8 + 7][lm] = v1.w;
        float4 w0 = *(const float4*)(bbase + (c0 + lm) * DIMK + kt + lseg * 8);
        float4 w1 = *(const float4*)(bbase + (c0 + lm) * DIMK + kt + lseg * 8 + 4);
        Bs[lseg * 8 + 0][lm] = w0.x; Bs[lseg * 8 + 1][lm] = w0.y;
        Bs[lseg * 8 + 2][lm] = w0.z; Bs[lseg * 8 + 3][lm] = w0.w;
        Bs[lseg * 8 + 4][lm] = w1.x; Bs[lseg * 8 + 5][lm] = w1.y;
        Bs[lseg * 8 + 6][lm] = w1.z; Bs[lseg * 8 + 7][lm] = w1.w;
        __syncthreads();
        #pragma unroll
        for (int k = 0; k < 32; k++) {
            float4 a = *(const float4*)&As[k][ty * 4];
            float4 bq = *(const float4*)&Bs[k][tx * 4];
            acc[0][0] = fmaf(a.x, bq.x, acc[0][0]); acc[0][1] = fmaf(a.x, bq.y, acc[0][1]);
            acc[0][2] = fmaf(a.x, bq.z, acc[0][2]); acc[0][3] = fmaf(a.x, bq.w, acc[0][3]);
            acc[1][0] = fmaf(a.y, bq.x, acc[1][0]); acc[1][1] = fmaf(a.y, bq.y, acc[1][1]);
            acc[1][2] = fmaf(a.y, bq.z, acc[1][2]); acc[1][3] = fmaf(a.y, bq.w, acc[1][3]);
            acc[2][0] = fmaf(a.z, bq.x, acc[2][0]); acc[2][1] = fmaf(a.z, bq.y, acc[2][1]);
            acc[2][2] = fmaf(a.z, bq.z, acc[2][2]); acc[2][3] = fmaf(a.z, bq.w, acc[2][3]);
            acc[3][0] = fmaf(a.w, bq.x, acc[3][0]); acc[3][1] = fmaf(a.w, bq.y, acc[3][1]);
            acc[3][2] = fmaf(a.w, bq.z, acc[3][2]); acc[3][3] = fmaf(a.w, bq.w, acc[3][3]);
        }
        __syncthreads();
    }

    if (z == 0) {
        float lsum = 0.f;
        #pragma unroll
        for (int ri = 0; ri < 4; ri++) {
            int r = r0 + ty * 4 + ri;
            int lr = labels[r];
            float ia = g_invRow[aIdx + r];
            #pragma unroll
            for (int ci = 0; ci < 4; ci++) {
                int c = c0 + tx * 4 + ci;
                float sv = acc[ri][ci] * ia * g_invRow[bIdx + c];
                lsum += (lr == labels[c]) ? softplusf(6.f - 10.f * sv)
                                          : softplusf(40.f * sv - 16.f);
            }
        }
        float tot = blockReduceSum(lsum, sred);
        if (tid == 0) atomicAdd(&g_accum[1], tot);
    } else {
        int p = z - 1;
        #pragma unroll
        for (int ri = 0; ri < 4; ri++) {
            int r = r0 + ty * 4 + ri;
            float ia = g_invRow[aIdx + r];
            #pragma unroll
            for (int ci = 0; ci < 4; ci++) {
                int c = c0 + tx * 4 + ci;
                g_sim[p * 65536 + r * 256 + c] = acc[ri][ci] * ia * g_invRow[bIdx + c];
            }
        }
    }
}

// ================= top-8 per row (z=0) / per column (z=1) =================
__global__ void k_top8() {
    int mode = blockIdx.z;
    int p = blockIdx.y;
    int w = threadIdx.x >> 5, lane = threadIdx.x & 31;
    int r = blockIdx.x * 8 + w;
    const float* base = g_sim + p * 65536;
    float v[8];
    #pragma unroll
    for (int j = 0; j < 8; j++) {
        int e = lane + j * 32;
        v[j] = mode ? base[e * 256 + r] : base[r * 256 + e];
    }
    int* out = (mode ? g_colTop : g_rowTop) + (p * 256 + r) * 8;
    for (int it = 0; it < 8; it++) {
        float bv = v[0]; int bj = 0;
        #pragma unroll
        for (int j = 1; j < 8; j++) if (v[j] > bv) { bv = v[j]; bj = j; }
        float mv = bv; int me = lane + bj * 32;
        #pragma unroll
        for (int o = 16; o; o >>= 1) {
            float ov = __shfl_xor_sync(0xffffffffu, mv, o);
            int oe = __shfl_xor_sync(0xffffffffu, me, o);
            if (ov > mv || (ov == mv && oe < me)) { mv = ov; me = oe; }
        }
        if (lane == 0) out[it] = me;
        if ((me & 31) == lane) v[me >> 5] = -__int_as_float(0x7f800000);
    }
}

// ================= local align with inline boost =================
__global__ void k_localb(const int* __restrict__ labels,
                         const int* __restrict__ vmask,
                         const int* __restrict__ tmask) {
    __shared__ unsigned char b1s[256];
    __shared__ int fwd2[8];
    __shared__ unsigned char hit2[8];
    __shared__ float sred[8];
    int p = blockIdx.y;
    int r = blockIdx.x;
    int tid = threadIdx.x;

    b1s[tid] = 0;
    __syncthreads();
    if (tid < 8) {
        int c = g_rowTop[(p * 256 + p) * 8 + tid];
        bool hit = false;
        #pragma unroll
        for (int m = 0; m < 8; m++) hit |= (g_colTop[(p * 256 + c) * 8 + m] == p);
        if (hit) b1s[c] = 1;
    } else if (tid < 16) {
        int k = tid - 8;
        int rr = g_colTop[(p * 256 + p) * 8 + k];
        bool hit = false;
        #pragma unroll
        for (int m = 0; m < 8; m++) hit |= (g_rowTop[(p * 256 + rr) * 8 + m] == p);
        fwd2[k] = rr;
        hit2[k] = hit ? 1 : 0;
    }
    __syncthreads();

    bool b2r = false;
    #pragma unroll
    for (int k = 0; k < 8; k++) b2r |= (fwd2[k] == r && hit2[k]);

    int c = tid;
    float s = g_sim[p * 65536 + r * 256 + c];
    bool match = labels[r] == labels[c];
    bool pm_r = vmask[r * NPART + p] != 0;
    bool pm_c = vmask[c * NPART + p] != 0;
    bool am_c = tmask[c * NPART + p] != 0;
    bool b1c = b1s[c] != 0;
    float Lp = softplusf(6.f - 10.f * s);
    float Ln = softplusf(40.f * s - 16.f);
    float v = 0.f;
    if (pm_r && am_c)          v += (match || b1c) ? Lp : Ln;   // b1 term
    if (pm_r && pm_c && am_c)  v += (match || b2r) ? Lp : Ln;   // b2 term (transposed)
    float tot = blockReduceSum(v, sred);
    if (tid == 0) atomicAdd(&g_accum[2], tot);
}

// ================= finalize =================
__global__ void k_final(float* __restrict__ out) {
    __shared__ float sred[512];
    int t = threadIdx.x;
    float v = logf(g_rowSumExp[t]) + SCALE_C - g_labelLogit[t];
    sred[t] = v;
    __syncthreads();
    for (int o = 256; o; o >>= 1) {
        if (t < o) sred[t] += sred[t + o];
        __syncthreads();
    }
    if (t == 0) {
        out[0] = sred[0] / 256.f;                                 // instance (v+t)
        out[1] = 5.f * g_accum[0] / (1280.f * 4096.f);            // mask
        out[2] = 2.f * g_accum[1] / 256.f;                        // global align
        out[3] = g_accum[2] / (5.f * 256.f);                      // local align
    }
}

// ---------------- launch: fork/join graph ----------------
extern "C" void kernel_launch(void* const* d_in, const int* in_sizes, int n_in,
                              void* d_out, int out_size) {
    const float* vis    = (const float*)d_in[0];
    const float* txt    = (const float*)d_in[1];
    const float* pe     = (const float*)d_in[2];
    const float* ae     = (const float*)d_in[3];
    const float* seg    = (const float*)d_in[4];
    const float* W      = (const float*)d_in[5];
    const int*   labels = (const int*)d_in[6];
    const int*   masks  = (const int*)d_in[7];
    const int*   vmask  = (const int*)d_in[8];
    const int*   tmask  = (const int*)d_in[9];
    float* out = (float*)d_out;

    static cudaStream_t sA = nullptr, sB = nullptr, sC = nullptr;
    static cudaEvent_t eRoot, ePrep, eMask, eNorm, eLocal;
    if (!sA) {
        cudaStreamCreateWithFlags(&sA, cudaStreamNonBlocking);
        cudaStreamCreateWithFlags(&sB, cudaStreamNonBlocking);
        cudaStreamCreateWithFlags(&sC, cudaStreamNonBlocking);
        cudaEventCreateWithFlags(&eRoot, cudaEventDisableTiming);
        cudaEventCreateWithFlags(&ePrep, cudaEventDisableTiming);
        cudaEventCreateWithFlags(&eMask, cudaEventDisableTiming);
        cudaEventCreateWithFlags(&eNorm, cudaEventDisableTiming);
        cudaEventCreateWithFlags(&eLocal, cudaEventDisableTiming);
        cudaFuncSetAttribute(k_mma, cudaFuncAttributeMaxDynamicSharedMemorySize, SM_TOTAL);
    }

    // root on capture stream (zeroes g_sumW before prepAW atomics)
    k_init0<<<43, 256>>>();
    cudaEventRecord(eRoot, 0);

    // branch A: operand prep + colnorm partials -> invW
    cudaStreamWaitEvent(sA, eRoot, 0);
    k_prepAW<<<NB_PREPA + NB_PREPW, 256, 0, sA>>>(vis, txt, W);
    k_rsqrtW<<<43, 256, 0, sA>>>();
    cudaEventRecord(ePrep, sA);

    // branch B: mask loss (independent)
    cudaStreamWaitEvent(sB, eRoot, 0);
    k_mask<<<1280, 256, 0, sB>>>(seg, masks);
    cudaEventRecord(eMask, sB);

    // main stream: row norms
    k_pre1<<<NB_ROWNORM, 256>>>(vis, txt, pe, ae);
    cudaEventRecord(eNorm, 0);

    // branch C: sim -> top8 -> localb (needs row norms)
    cudaStreamWaitEvent(sC, eNorm, 0);
    k_sim<<<dim3(4, 4, 6), 256, 0, sC>>>(vis, txt, pe, ae, labels);
    k_top8<<<dim3(32, NPART, 2), 256, 0, sC>>>();
    k_localb<<<dim3(256, NPART), 256, 0, sC>>>(labels, vmask, tmask);
    cudaEventRecord(eLocal, sC);

    // main stream: mma (needs prep/invW + row norms), then join + finalize
    cudaStreamWaitEvent(0, ePrep, 0);
    k_mma<<<NB_MMA, 256, SM_TOTAL>>>(labels);
    cudaStreamWaitEvent(0, eMask, 0);
    cudaStreamWaitEvent(0, eLocal, 0);
    k_final<<<1, 512>>>(out);
}

// round 11
// speedup vs baseline: 1.5845x; 1.5845x over previous
#include <cuda_runtime.h>
#include <cuda_bf16.h>
#include <cstdint>

#define DIMK   512
#define NCLS   11003
#define NCPAD  11008
#define NPART  5
#define NSEGC  6
#define NPIX   4096
#define SCALE_C 28.0f

// ---------------- device scratch ----------------
__device__ float g_invW[NCPAD];
__device__ float g_invRow[3072];          // [0,512) v|t, [512,1792) part, [1792,3072) attr
__device__ float g_rowSumExp[512];
__device__ float g_labelLogit[512];
__device__ float g_sim[NPART * 256 * 256];
__device__ int   g_rowTop[NPART * 256 * 8];
__device__ int   g_colTop[NPART * 256 * 8];
__device__ float g_accum[4];              // 0: mask ce, 1: global, 2: local

// bf16 operands (UNNORMALIZED; norms applied in epilogues). W transposed K-major.
__device__ __align__(16) __nv_bfloat16 g_Ahi[512 * DIMK];
__device__ __align__(16) __nv_bfloat16 g_Whi[NCPAD * DIMK];

// ---------------- helpers ----------------
__device__ __forceinline__ uint32_t smem_u32(const void* p) {
    uint32_t a;
    asm("{ .reg .u64 t; cvta.to.shared.u64 t, %1; cvt.u32.u64 %0, t; }" : "=r"(a) : "l"(p));
    return a;
}
#define CP16(dst, src) asm volatile("cp.async.cg.shared.global [%0], [%1], 16;" :: "r"(dst), "l"(src))
#define CP_COMMIT()    asm volatile("cp.async.commit_group;" ::: "memory")

__device__ __forceinline__ void ldm4(uint32_t* r, uint32_t addr) {
    asm volatile("ldmatrix.sync.aligned.m8n8.x4.shared.b16 {%0,%1,%2,%3}, [%4];"
                 : "=r"(r[0]), "=r"(r[1]), "=r"(r[2]), "=r"(r[3]) : "r"(addr));
}
__device__ __forceinline__ void mma16816(float* c, const uint32_t* a, uint32_t b0, uint32_t b1) {
    asm volatile("mma.sync.aligned.m16n8k16.row.col.f32.bf16.bf16.f32 "
                 "{%0,%1,%2,%3}, {%4,%5,%6,%7}, {%8,%9}, {%0,%1,%2,%3};"
                 : "+f"(c[0]), "+f"(c[1]), "+f"(c[2]), "+f"(c[3])
                 : "r"(a[0]), "r"(a[1]), "r"(a[2]), "r"(a[3]), "r"(b0), "r"(b1));
}

__device__ __forceinline__ float softplusf(float x) {
    return x > 15.f ? x : log1pf(__expf(x));
}
__device__ __forceinline__ float blockReduceSum(float v, float* sh) {
    int t = threadIdx.x;
    #pragma unroll
    for (int o = 16; o; o >>= 1) v += __shfl_xor_sync(0xffffffffu, v, o);
    if ((t & 31) == 0) sh[t >> 5] = v;
    __syncthreads();
    int nw = (blockDim.x + 31) >> 5;
    if (t < 32) {
        v = (t < nw) ? sh[t] : 0.f;
        #pragma unroll
        for (int o = 16; o; o >>= 1) v += __shfl_xor_sync(0xffffffffu, v, o);
    }
    return v;
}

// ================= init0 =================
__global__ void k_init0() {
    int t = threadIdx.x;
    if (t < 512) { g_rowSumExp[t] = 0.f; g_labelLogit[t] = 0.f; }
    if (t < 4) g_accum[t] = 0.f;
}

// ================= colnorm: 8-way parallel per column =================
#define NB_COLNORM 344
__global__ __launch_bounds__(256) void k_colnorm(const float* __restrict__ W) {
    __shared__ float sh[8][32];
    int c0 = blockIdx.x * 32;
    int col = threadIdx.x & 31;
    int grp = threadIdx.x >> 5;
    int c = c0 + col;
    float s = 0.f;
    if (c < NCLS) {
        #pragma unroll 4
        for (int d = grp; d < DIMK; d += 8) {
            float w = W[d * NCLS + c];
            s = fmaf(w, w, s);
        }
    }
    sh[grp][col] = s;
    __syncthreads();
    if (grp == 0) {
        float tot = sh[0][col];
        #pragma unroll
        for (int g = 1; g < 8; g++) tot += sh[g][col];
        g_invW[c0 + col] = (c < NCLS) ? rsqrtf(tot) : 0.f;
    }
}

// ================= pre1: row norms =================
#define NB_ROWNORM 384
__global__ __launch_bounds__(256) void k_pre1(
    const float* __restrict__ vis, const float* __restrict__ txt,
    const float* __restrict__ pe, const float* __restrict__ ae) {
    int warp = blockIdx.x * 8 + (threadIdx.x >> 5);
    int lane = threadIdx.x & 31;
    const float* src;
    if (warp < 256)       src = vis + warp * DIMK;
    else if (warp < 512)  src = txt + (warp - 256) * DIMK;
    else if (warp < 1792) src = pe + (warp - 512) * DIMK;
    else                  src = ae + (warp - 1792) * DIMK;
    float s = 0.f;
    #pragma unroll 4
    for (int j = lane; j < DIMK; j += 32) { float v = src[j]; s = fmaf(v, v, s); }
    #pragma unroll
    for (int o = 16; o; o >>= 1) s += __shfl_xor_sync(0xffffffffu, s, o);
    if (!lane) g_invRow[warp] = rsqrtf(s);
}

// ================= prepAW: bf16 conversion (A) + transpose-convert (W) =================
#define NB_PREPA 128
#define NB_PREPW 5504        /* 344 x 16 */
__global__ __launch_bounds__(256) void k_prepAW(
    const float* __restrict__ vis, const float* __restrict__ txt,
    const float* __restrict__ W) {
    __shared__ float sh[32][33];
    int b = blockIdx.x;
    int tid = threadIdx.x;
    if (b < NB_PREPA) {
        #pragma unroll
        for (int rr = 0; rr < 4; rr++) {
            int row = b * 4 + rr;
            const float* src = (row < 256) ? (vis + row * DIMK) : (txt + (row - 256) * DIMK);
            for (int j = tid; j < DIMK; j += 256)
                g_Ahi[row * DIMK + j] = __float2bfloat16(src[j]);
        }
    } else {
        int w = b - NB_PREPA;
        int c0 = (w % 344) * 32;
        int d0 = (w / 344) * 32;
        int tx = tid & 31;
        int ty = tid >> 5;
        #pragma unroll
        for (int j = 0; j < 4; j++) {
            int d = d0 + ty + j * 8;
            int c = c0 + tx;
            sh[ty + j * 8][tx] = (c < NCLS) ? W[d * NCLS + c] : 0.f;
        }
        __syncthreads();
        #pragma unroll
        for (int j = 0; j < 4; j++) {
            int cl = ty + j * 8;
            g_Whi[(c0 + cl) * DIMK + d0 + tx] = __float2bfloat16(sh[tx][cl]);
        }
    }
}

// ================= mma v2: M128 x N128 tile, K-chunk 64, 3-stage cp.async =================
#define ROWB       144                    /* 128B data + 16B pad, odd 16B multiple */
#define A_BYTES    (128 * ROWB)           /* 18432 */
#define STAGE      (2 * A_BYTES)          /* 36864: A then B */
#define OFF_A      0
#define OFF_B      A_BYTES
#define SM_TOTAL   (3 * STAGE)            /* 110592 */
#define NB_MMA     344                    /* 86 col tiles x 4 row tiles */

__global__ __launch_bounds__(256, 2) void k_mma(const int* __restrict__ labels) {
    extern __shared__ char smem[];
    const int tid = threadIdx.x;
    const int wid = tid >> 5, lane = tid & 31;
    const int row0 = (blockIdx.x & 3) * 128;       // col-tile-major: W tile L2 reuse
    const int col0 = (blockIdx.x >> 2) * 128;
    const int warpM = wid & 3;                     // 4 x 32 rows
    const int warpN = wid >> 2;                    // 2 x 64 cols
    const uint32_t sbase = smem_u32(smem);

    float acc[2][8][4];
    #pragma unroll
    for (int i = 0; i < 2; i++)
        #pragma unroll
        for (int j = 0; j < 8; j++)
            #pragma unroll
            for (int k = 0; k < 4; k++) acc[i][j][k] = 0.f;

    const int lr = tid >> 1, lh = tid & 1;         // 128 rows x 2 64B-halves
    auto load_chunk = [&](int kc, int buf) {
        uint32_t bb = sbase + buf * STAGE;
        const __nv_bfloat16* sa = g_Ahi + (long)(row0 + lr) * DIMK + kc * 64 + lh * 32;
        uint32_t da = bb + OFF_A + lr * ROWB + lh * 64;
        CP16(da, sa); CP16(da + 16, sa + 8); CP16(da + 32, sa + 16); CP16(da + 48, sa + 24);
        const __nv_bfloat16* sb = g_Whi + (long)(col0 + lr) * DIMK + kc * 64 + lh * 32;
        uint32_t db = bb + OFF_B + lr * ROWB + lh * 64;
        CP16(db, sb); CP16(db + 16, sb + 8); CP16(db + 32, sb + 16); CP16(db + 48, sb + 24);
    };

    load_chunk(0, 0); CP_COMMIT();
    load_chunk(1, 1); CP_COMMIT();
    load_chunk(2, 2); CP_COMMIT();

    for (int kc = 0; kc < 8; kc++) {
        if (kc < 6)      asm volatile("cp.async.wait_group 2;" ::: "memory");
        else if (kc == 6) asm volatile("cp.async.wait_group 1;" ::: "memory");
        else              asm volatile("cp.async.wait_group 0;" ::: "memory");
        __syncthreads();

        uint32_t bb = sbase + (kc % 3) * STAGE;
        #pragma unroll
        for (int ks = 0; ks < 4; ks++) {
            uint32_t ah[2][4], bh[4][4];
            #pragma unroll
            for (int mi = 0; mi < 2; mi++) {
                uint32_t ra = (uint32_t)((warpM * 32 + mi * 16 + (lane & 15)) * ROWB +
                                         ks * 32 + (lane >> 4) * 16);
                ldm4(ah[mi], bb + OFF_A + ra);
            }
            #pragma unroll
            for (int j = 0; j < 4; j++) {
                uint32_t rb = (uint32_t)((warpN * 64 + j * 16 + ((lane >> 4) << 3) + (lane & 7)) * ROWB +
                                         ks * 32 + ((lane >> 3) & 1) * 16);
                ldm4(bh[j], bb + OFF_B + rb);
            }
            #pragma unroll
            for (int mi = 0; mi < 2; mi++) {
                #pragma unroll
                for (int ni = 0; ni < 8; ni++) {
                    int j = ni >> 1, loc = ni & 1;
                    mma16816(acc[mi][ni], ah[mi], bh[j][loc * 2], bh[j][loc * 2 + 1]);
                }
            }
        }
        __syncthreads();
        int nx = kc + 3;
        if (nx < 8) { load_chunk(nx, nx % 3); CP_COMMIT(); }
    }

    // epilogue: apply norms, shifted sumexp + label capture
    int q = lane >> 2, qc = lane & 3;
    #pragma unroll
    for (int mi = 0; mi < 2; mi++) {
        #pragma unroll
        for (int half = 0; half < 2; half++) {
            int row = row0 + warpM * 32 + mi * 16 + half * 8 + q;
            float invA = SCALE_C * g_invRow[row];
            int lbl = labels[row & 255];
            float rs = 0.f;
            #pragma unroll
            for (int ni = 0; ni < 8; ni++) {
                #pragma unroll
                for (int j = 0; j < 2; j++) {
                    int c = col0 + warpN * 64 + ni * 8 + qc * 2 + j;
                    if (c < NCLS) {
                        float lg = acc[mi][ni][half * 2 + j] * invA * g_invW[c];
                        rs += __expf(lg - SCALE_C);
                        if (c == lbl) g_labelLogit[row] = lg;
                    }
                }
            }
            rs += __shfl_xor_sync(0xffffffffu, rs, 1);
            rs += __shfl_xor_sync(0xffffffffu, rs, 2);
            if (qc == 0) atomicAdd(&g_rowSumExp[row], rs);
        }
    }
}

// ================= mask loss (parallel stream) =================
__global__ __launch_bounds__(256) void k_mask(const float* __restrict__ seg,
                                              const int* __restrict__ masks) {
    __shared__ float sred[8];
    int n = blockIdx.x;
    int tid = threadIdx.x;
    const float4* base4 = (const float4*)(seg + (long long)n * NSEGC * NPIX);
    const int4* mb4 = (const int4*)(masks + n * NPIX);
    float lsum = 0.f;
    auto ce = [&](float a0, float a1, float a2, float a3, float a4, float a5, int k) {
        float m = fmaxf(fmaxf(fmaxf(a0, a1), fmaxf(a2, a3)), fmaxf(a4, a5));
        float s = __expf(a0 - m) + __expf(a1 - m) + __expf(a2 - m) +
                  __expf(a3 - m) + __expf(a4 - m) + __expf(a5 - m);
        float pk = k == 0 ? a0 : k == 1 ? a1 : k == 2 ? a2 : k == 3 ? a3 : k == 4 ? a4 : a5;
        lsum += m + __logf(s) - pk;
    };
    #pragma unroll
    for (int it = 0; it < 4; it++) {
        int pidx = tid + it * 256;
        float4 x[NSEGC];
        #pragma unroll
        for (int ch = 0; ch < NSEGC; ch++) x[ch] = base4[ch * 1024 + pidx];
        int4 kk = mb4[pidx];
        ce(x[0].x, x[1].x, x[2].x, x[3].x, x[4].x, x[5].x, kk.x);
        ce(x[0].y, x[1].y, x[2].y, x[3].y, x[4].y, x[5].y, kk.y);
        ce(x[0].z, x[1].z, x[2].z, x[3].z, x[4].z, x[5].z, kk.z);
        ce(x[0].w, x[1].w, x[2].w, x[3].w, x[4].w, x[5].w, kk.w);
    }
    float tot = blockReduceSum(lsum, sred);
    if (tid == 0) atomicAdd(&g_accum[0], tot);
}

// ================= sim GEMMs (z=0 global align fused; z=1..5 to scratch) =================
__global__ __launch_bounds__(256) void k_sim(
    const float* __restrict__ vis, const float* __restrict__ txt,
    const float* __restrict__ pe, const float* __restrict__ ae,
    const int* __restrict__ labels) {
    __shared__ float As[32][68];
    __shared__ float Bs[32][68];
    __shared__ float sred[8];
    int z = blockIdx.z;
    int tid = threadIdx.x;
    int tx = tid & 15, ty = tid >> 4;
    int r0 = blockIdx.y * 64, c0 = blockIdx.x * 64;

    const float* abase; const float* bbase; int aIdx, bIdx;
    if (z == 0) { abase = vis; bbase = txt; aIdx = 0; bIdx = 256; }
    else {
        int p = z - 1;
        abase = pe + p * 256 * DIMK; bbase = ae + p * 256 * DIMK;
        aIdx = 512 + p * 256; bIdx = 1792 + p * 256;
    }

    float acc[4][4];
    #pragma unroll
    for (int i = 0; i < 4; i++)
        #pragma unroll
        for (int j = 0; j < 4; j++) acc[i][j] = 0.f;

    int lm = tid >> 2, lseg = tid & 3;
    for (int kt = 0; kt < DIMK; kt += 32) {
        float4 v0 = *(const float4*)(abase + (r0 + lm) * DIMK + kt + lseg * 8);
        float4 v1 = *(const float4*)(abase + (r0 + lm) * DIMK + kt + lseg * 8 + 4);
        As[lseg * 8 + 0][lm] = v0.x; As[lseg * 8 + 1][lm] = v0.y;
        As[lseg * 8 + 2][lm] = v0.z; As[lseg * 8 + 3][lm] = v0.w;
        As[lseg * 8 + 4][lm] = v1.x; As[lseg * 8 + 5][lm] = v1.y;
        As[lseg * 8 + 6][lm] = v1.z; As[lseg * 8 + 7][lm] = v1.w;
        float4 w0 = *(const float4*)(bbase + (c0 + lm) * DIMK + kt + lseg * 8);
        float4 w1 = *(const float4*)(bbase + (c0 + lm) * DIMK + kt + lseg * 8 + 4);
        Bs[lseg * 8 + 0][lm] = w0.x; Bs[lseg * 8 + 1][lm] = w0.y;
        Bs[lseg * 8 + 2][lm] = w0.z; Bs[lseg * 8 + 3][lm] = w0.w;
        Bs[lseg * 8 + 4][lm] = w1.x; Bs[lseg * 8 + 5][lm] = w1.y;
        Bs[lseg * 8 + 6][lm] = w1.z; Bs[lseg * 8 + 7][lm] = w1.w;
        __syncthreads();
        #pragma unroll
        for (int k = 0; k < 32; k++) {
            float4 a = *(const float4*)&As[k][ty * 4];
            float4 bq = *(const float4*)&Bs[k][tx * 4];
            acc[0][0] = fmaf(a.x, bq.x, acc[0][0]); acc[0][1] = fmaf(a.x, bq.y, acc[0][1]);
            acc[0][2] = fmaf(a.x, bq.z, acc[0][2]); acc[0][3] = fmaf(a.x, bq.w, acc[0][3]);
            acc[1][0] = fmaf(a.y, bq.x, acc[1][0]); acc[1][1] = fmaf(a.y, bq.y, acc[1][1]);
            acc[1][2] = fmaf(a.y, bq.z, acc[1][2]); acc[1][3] = fmaf(a.y, bq.w, acc[1][3]);
            acc[2][0] = fmaf(a.z, bq.x, acc[2][0]); acc[2][1] = fmaf(a.z, bq.y, acc[2][1]);
            acc[2][2] = fmaf(a.z, bq.z, acc[2][2]); acc[2][3] = fmaf(a.z, bq.w, acc[2][3]);
            acc[3][0] = fmaf(a.w, bq.x, acc[3][0]); acc[3][1] = fmaf(a.w, bq.y, acc[3][1]);
            acc[3][2] = fmaf(a.w, bq.z, acc[3][2]); acc[3][3] = fmaf(a.w, bq.w, acc[3][3]);
        }
        __syncthreads();
    }

    if (z == 0) {
        float lsum = 0.f;
        #pragma unroll
        for (int ri = 0; ri < 4; ri++) {
            int r = r0 + ty * 4 + ri;
            int lr = labels[r];
            float ia = g_invRow[aIdx + r];
            #pragma unroll
            for (int ci = 0; ci < 4; ci++) {
                int c = c0 + tx * 4 + ci;
                float sv = acc[ri][ci] * ia * g_invRow[bIdx + c];
                lsum += (lr == labels[c]) ? softplusf(6.f - 10.f * sv)
                                          : softplusf(40.f * sv - 16.f);
            }
        }
        float tot = blockReduceSum(lsum, sred);
        if (tid == 0) atomicAdd(&g_accum[1], tot);
    } else {
        int p = z - 1;
        #pragma unroll
        for (int ri = 0; ri < 4; ri++) {
            int r = r0 + ty * 4 + ri;
            float ia = g_invRow[aIdx + r];
            #pragma unroll
            for (int ci = 0; ci < 4; ci++) {
                int c = c0 + tx * 4 + ci;
                g_sim[p * 65536 + r * 256 + c] = acc[ri][ci] * ia * g_invRow[bIdx + c];
            }
        }
    }
}

// ================= top-8 per row (z=0) / per column (z=1) =================
__global__ void k_top8() {
    int mode = blockIdx.z;
    int p = blockIdx.y;
    int w = threadIdx.x >> 5, lane = threadIdx.x & 31;
    int r = blockIdx.x * 8 + w;
    const float* base = g_sim + p * 65536;
    float v[8];
    #pragma unroll
    for (int j = 0; j < 8; j++) {
        int e = lane + j * 32;
        v[j] = mode ? base[e * 256 + r] : base[r * 256 + e];
    }
    int* out = (mode ? g_colTop : g_rowTop) + (p * 256 + r) * 8;
    for (int it = 0; it < 8; it++) {
        float bv = v[0]; int bj = 0;
        #pragma unroll
        for (int j = 1; j < 8; j++) if (v[j] > bv) { bv = v[j]; bj = j; }
        float mv = bv; int me = lane + bj * 32;
        #pragma unroll
        for (int o = 16; o; o >>= 1) {
            float ov = __shfl_xor_sync(0xffffffffu, mv, o);
            int oe = __shfl_xor_sync(0xffffffffu, me, o);
            if (ov > mv || (ov == mv && oe < me)) { mv = ov; me = oe; }
        }
        if (lane == 0) out[it] = me;
        if ((me & 31) == lane) v[me >> 5] = -__int_as_float(0x7f800000);
    }
}

// ================= local align with inline boost =================
__global__ void k_localb(const int* __restrict__ labels,
                         const int* __restrict__ vmask,
                         const int* __restrict__ tmask) {
    __shared__ unsigned char b1s[256];
    __shared__ int fwd2[8];
    __shared__ unsigned char hit2[8];
    __shared__ float sred[8];
    int p = blockIdx.y;
    int r = blockIdx.x;
    int tid = threadIdx.x;

    b1s[tid] = 0;
    __syncthreads();
    if (tid < 8) {
        int c = g_rowTop[(p * 256 + p) * 8 + tid];
        bool hit = false;
        #pragma unroll
        for (int m = 0; m < 8; m++) hit |= (g_colTop[(p * 256 + c) * 8 + m] == p);
        if (hit) b1s[c] = 1;
    } else if (tid < 16) {
        int k = tid - 8;
        int rr = g_colTop[(p * 256 + p) * 8 + k];
        bool hit = false;
        #pragma unroll
        for (int m = 0; m < 8; m++) hit |= (g_rowTop[(p * 256 + rr) * 8 + m] == p);
        fwd2[k] = rr;
        hit2[k] = hit ? 1 : 0;
    }
    __syncthreads();

    bool b2r = false;
    #pragma unroll
    for (int k = 0; k < 8; k++) b2r |= (fwd2[k] == r && hit2[k]);

    int c = tid;
    float s = g_sim[p * 65536 + r * 256 + c];
    bool match = labels[r] == labels[c];
    bool pm_r = vmask[r * NPART + p] != 0;
    bool pm_c = vmask[c * NPART + p] != 0;
    bool am_c = tmask[c * NPART + p] != 0;
    bool b1c = b1s[c] != 0;
    float Lp = softplusf(6.f - 10.f * s);
    float Ln = softplusf(40.f * s - 16.f);
    float v = 0.f;
    if (pm_r && am_c)          v += (match || b1c) ? Lp : Ln;   // b1 term
    if (pm_r && pm_c && am_c)  v += (match || b2r) ? Lp : Ln;   // b2 term (transposed)
    float tot = blockReduceSum(v, sred);
    if (tid == 0) atomicAdd(&g_accum[2], tot);
}

// ================= finalize =================
__global__ void k_final(float* __restrict__ out) {
    __shared__ float sred[512];
    int t = threadIdx.x;
    float v = logf(g_rowSumExp[t]) + SCALE_C - g_labelLogit[t];
    sred[t] = v;
    __syncthreads();
    for (int o = 256; o; o >>= 1) {
        if (t < o) sred[t] += sred[t + o];
        __syncthreads();
    }
    if (t == 0) {
        out[0] = sred[0] / 256.f;                                 // instance (v+t)
        out[1] = 5.f * g_accum[0] / (1280.f * 4096.f);            // mask
        out[2] = 2.f * g_accum[1] / 256.f;                        // global align
        out[3] = g_accum[2] / (5.f * 256.f);                      // local align
    }
}

// ---------------- launch: fork/join graph ----------------
extern "C" void kernel_launch(void* const* d_in, const int* in_sizes, int n_in,
                              void* d_out, int out_size) {
    const float* vis    = (const float*)d_in[0];
    const float* txt    = (const float*)d_in[1];
    const float* pe     = (const float*)d_in[2];
    const float* ae     = (const float*)d_in[3];
    const float* seg    = (const float*)d_in[4];
    const float* W      = (const float*)d_in[5];
    const int*   labels = (const int*)d_in[6];
    const int*   masks  = (const int*)d_in[7];
    const int*   vmask  = (const int*)d_in[8];
    const int*   tmask  = (const int*)d_in[9];
    float* out = (float*)d_out;

    static cudaStream_t sA = nullptr, sB = nullptr, sC = nullptr;
    static cudaEvent_t eRoot, ePrep, eMask, eNorm, eLocal;
    if (!sA) {
        cudaStreamCreateWithFlags(&sA, cudaStreamNonBlocking);
        cudaStreamCreateWithFlags(&sB, cudaStreamNonBlocking);
        cudaStreamCreateWithFlags(&sC, cudaStreamNonBlocking);
        cudaEventCreateWithFlags(&eRoot, cudaEventDisableTiming);
        cudaEventCreateWithFlags(&ePrep, cudaEventDisableTiming);
        cudaEventCreateWithFlags(&eMask, cudaEventDisableTiming);
        cudaEventCreateWithFlags(&eNorm, cudaEventDisableTiming);
        cudaEventCreateWithFlags(&eLocal, cudaEventDisableTiming);
        cudaFuncSetAttribute(k_mma, cudaFuncAttributeMaxDynamicSharedMemorySize, SM_TOTAL);
    }

    // root
    k_init0<<<1, 512>>>();
    cudaEventRecord(eRoot, 0);

    // branch A: colnorm -> operand prep (feeds mma)
    cudaStreamWaitEvent(sA, eRoot, 0);
    k_colnorm<<<NB_COLNORM, 256, 0, sA>>>(W);
    k_prepAW<<<NB_PREPA + NB_PREPW, 256, 0, sA>>>(vis, txt, W);
    cudaEventRecord(ePrep, sA);

    // branch B: mask loss (independent)
    cudaStreamWaitEvent(sB, eRoot, 0);
    k_mask<<<1280, 256, 0, sB>>>(seg, masks);
    cudaEventRecord(eMask, sB);

    // main stream: row norms
    k_pre1<<<NB_ROWNORM, 256>>>(vis, txt, pe, ae);
    cudaEventRecord(eNorm, 0);

    // branch C: sim -> top8 -> localb (needs row norms)
    cudaStreamWaitEvent(sC, eNorm, 0);
    k_sim<<<dim3(4, 4, 6), 256, 0, sC>>>(vis, txt, pe, ae, labels);
    k_top8<<<dim3(32, NPART, 2), 256, 0, sC>>>();
    k_localb<<<dim3(256, NPART), 256, 0, sC>>>(labels, vmask, tmask);
    cudaEventRecord(eLocal, sC);

    // main stream: mma (needs prep + row norms), then join + finalize
    cudaStreamWaitEvent(0, ePrep, 0);
    k_mma<<<NB_MMA, 256, SM_TOTAL>>>(labels);
    cudaStreamWaitEvent(0, eMask, 0);
    cudaStreamWaitEvent(0, eLocal, 0);
    k_final<<<1, 512>>>(out);
}

// round 12
// speedup vs baseline: 1.6734x; 1.0561x over previous
#include <cuda_runtime.h>
#include <cuda_bf16.h>
#include <cstdint>

#define DIMK   512
#define NCLS   11003
#define NCPAD  11008
#define NPART  5
#define NSEGC  6
#define NPIX   4096
#define SCALE_C 28.0f

// ---------------- device scratch ----------------
__device__ float g_invW[NCPAD];
__device__ float g_invRow[3072];          // [0,512) v|t, [512,1792) part, [1792,3072) attr
__device__ float g_rowSumExp[512];
__device__ float g_labelLogit[512];
__device__ float g_sim[NPART * 256 * 256];
__device__ int   g_rowTop[NPART * 256 * 8];
__device__ int   g_colTop[NPART * 256 * 8];
__device__ float g_accum[4];              // 0: mask ce, 1: global, 2: local

// bf16 operands (UNNORMALIZED; norms applied in epilogues). W transposed K-major.
__device__ __align__(16) __nv_bfloat16 g_Ahi[512 * DIMK];
__device__ __align__(16) __nv_bfloat16 g_Whi[NCPAD * DIMK];

// ---------------- helpers ----------------
__device__ __forceinline__ uint32_t smem_u32(const void* p) {
    uint32_t a;
    asm("{ .reg .u64 t; cvta.to.shared.u64 t, %1; cvt.u32.u64 %0, t; }" : "=r"(a) : "l"(p));
    return a;
}
#define CP16(dst, src) asm volatile("cp.async.cg.shared.global [%0], [%1], 16;" :: "r"(dst), "l"(src))
#define CP_COMMIT()    asm volatile("cp.async.commit_group;" ::: "memory")

__device__ __forceinline__ void ldm4(uint32_t* r, uint32_t addr) {
    asm volatile("ldmatrix.sync.aligned.m8n8.x4.shared.b16 {%0,%1,%2,%3}, [%4];"
                 : "=r"(r[0]), "=r"(r[1]), "=r"(r[2]), "=r"(r[3]) : "r"(addr));
}
__device__ __forceinline__ void mma16816(float* c, const uint32_t* a, uint32_t b0, uint32_t b1) {
    asm volatile("mma.sync.aligned.m16n8k16.row.col.f32.bf16.bf16.f32 "
                 "{%0,%1,%2,%3}, {%4,%5,%6,%7}, {%8,%9}, {%0,%1,%2,%3};"
                 : "+f"(c[0]), "+f"(c[1]), "+f"(c[2]), "+f"(c[3])
                 : "r"(a[0]), "r"(a[1]), "r"(a[2]), "r"(a[3]), "r"(b0), "r"(b1));
}

__device__ __forceinline__ float softplusf(float x) {
    return x > 15.f ? x : log1pf(__expf(x));
}
__device__ __forceinline__ float blockReduceSum(float v, float* sh) {
    int t = threadIdx.x;
    #pragma unroll
    for (int o = 16; o; o >>= 1) v += __shfl_xor_sync(0xffffffffu, v, o);
    if ((t & 31) == 0) sh[t >> 5] = v;
    __syncthreads();
    int nw = (blockDim.x + 31) >> 5;
    if (t < 32) {
        v = (t < nw) ? sh[t] : 0.f;
        #pragma unroll
        for (int o = 16; o; o >>= 1) v += __shfl_xor_sync(0xffffffffu, v, o);
    }
    return v;
}

// ================= init0 =================
__global__ void k_init0() {
    int t = threadIdx.x;
    if (t < 512) { g_rowSumExp[t] = 0.f; g_labelLogit[t] = 0.f; }
    if (t < 4) g_accum[t] = 0.f;
}

// ================= pre1: row norms =================
#define NB_ROWNORM 384
__global__ __launch_bounds__(256) void k_pre1(
    const float* __restrict__ vis, const float* __restrict__ txt,
    const float* __restrict__ pe, const float* __restrict__ ae) {
    int warp = blockIdx.x * 8 + (threadIdx.x >> 5);
    int lane = threadIdx.x & 31;
    const float* src;
    if (warp < 256)       src = vis + warp * DIMK;
    else if (warp < 512)  src = txt + (warp - 256) * DIMK;
    else if (warp < 1792) src = pe + (warp - 512) * DIMK;
    else                  src = ae + (warp - 1792) * DIMK;
    float s = 0.f;
    #pragma unroll 4
    for (int j = lane; j < DIMK; j += 32) { float v = src[j]; s = fmaf(v, v, s); }
    #pragma unroll
    for (int o = 16; o; o >>= 1) s += __shfl_xor_sync(0xffffffffu, s, o);
    if (!lane) g_invRow[warp] = rsqrtf(s);
}

// ================= prepAW: A convert + W single-pass colnorm+transpose-convert =================
// A blocks: 128 (4 rows each). W blocks: 344, each owns a 32-column strip and loops
// all 16 d-tiles, accumulating per-column sumsq in registers (no atomics).
#define NB_PREPA 128
#define NB_PREPW 344
__global__ __launch_bounds__(256) void k_prepAW(
    const float* __restrict__ vis, const float* __restrict__ txt,
    const float* __restrict__ W) {
    __shared__ float sh[32][33];
    int b = blockIdx.x;
    int tid = threadIdx.x;
    if (b < NB_PREPA) {
        #pragma unroll
        for (int rr = 0; rr < 4; rr++) {
            int row = b * 4 + rr;
            const float* src = (row < 256) ? (vis + row * DIMK) : (txt + (row - 256) * DIMK);
            for (int j = tid; j < DIMK; j += 256)
                g_Ahi[row * DIMK + j] = __float2bfloat16(src[j]);
        }
    } else {
        int c0 = (b - NB_PREPA) * 32;
        int tx = tid & 31;   // lane
        int ty = tid >> 5;   // warp 0..7
        float ss[4] = {0.f, 0.f, 0.f, 0.f};
        for (int d0 = 0; d0 < DIMK; d0 += 32) {
            #pragma unroll
            for (int j = 0; j < 4; j++) {
                int d = d0 + ty + j * 8;
                int c = c0 + tx;
                sh[ty + j * 8][tx] = (c < NCLS) ? W[d * NCLS + c] : 0.f;
            }
            __syncthreads();
            #pragma unroll
            for (int j = 0; j < 4; j++) {
                int cl = ty + j * 8;               // column-local; d = d0 + tx
                float x = sh[tx][cl];
                g_Whi[(c0 + cl) * DIMK + d0 + tx] = __float2bfloat16(x);
                ss[j] = fmaf(x, x, ss[j]);
            }
            __syncthreads();
        }
        // reduce sumsq over lanes (d-offsets) per column; warp ty owns cols ty + j*8
        #pragma unroll
        for (int j = 0; j < 4; j++) {
            float s = ss[j];
            #pragma unroll
            for (int o = 16; o; o >>= 1) s += __shfl_xor_sync(0xffffffffu, s, o);
            if (tx == 0) g_invW[c0 + ty + j * 8] = rsqrtf(s);
        }
    }
}

// ================= mma v2: M128 x N128 tile, K-chunk 64, 3-stage cp.async =================
#define ROWB       144                    /* 128B data + 16B pad, odd 16B multiple */
#define A_BYTES    (128 * ROWB)           /* 18432 */
#define STAGE      (2 * A_BYTES)          /* 36864: A then B */
#define OFF_A      0
#define OFF_B      A_BYTES
#define SM_TOTAL   (3 * STAGE)            /* 110592 */
#define NB_MMA     344                    /* 86 col tiles x 4 row tiles */

__global__ __launch_bounds__(256, 2) void k_mma(const int* __restrict__ labels) {
    extern __shared__ char smem[];
    const int tid = threadIdx.x;
    const int wid = tid >> 5, lane = tid & 31;
    const int row0 = (blockIdx.x & 3) * 128;       // col-tile-major: W tile L2 reuse
    const int col0 = (blockIdx.x >> 2) * 128;
    const int warpM = wid & 3;                     // 4 x 32 rows
    const int warpN = wid >> 2;                    // 2 x 64 cols
    const uint32_t sbase = smem_u32(smem);

    float acc[2][8][4];
    #pragma unroll
    for (int i = 0; i < 2; i++)
        #pragma unroll
        for (int j = 0; j < 8; j++)
            #pragma unroll
            for (int k = 0; k < 4; k++) acc[i][j][k] = 0.f;

    const int lr = tid >> 1, lh = tid & 1;         // 128 rows x 2 64B-halves
    auto load_chunk = [&](int kc, int buf) {
        uint32_t bb = sbase + buf * STAGE;
        const __nv_bfloat16* sa = g_Ahi + (long)(row0 + lr) * DIMK + kc * 64 + lh * 32;
        uint32_t da = bb + OFF_A + lr * ROWB + lh * 64;
        CP16(da, sa); CP16(da + 16, sa + 8); CP16(da + 32, sa + 16); CP16(da + 48, sa + 24);
        const __nv_bfloat16* sb = g_Whi + (long)(col0 + lr) * DIMK + kc * 64 + lh * 32;
        uint32_t db = bb + OFF_B + lr * ROWB + lh * 64;
        CP16(db, sb); CP16(db + 16, sb + 8); CP16(db + 32, sb + 16); CP16(db + 48, sb + 24);
    };

    load_chunk(0, 0); CP_COMMIT();
    load_chunk(1, 1); CP_COMMIT();
    load_chunk(2, 2); CP_COMMIT();

    for (int kc = 0; kc < 8; kc++) {
        if (kc < 6)      asm volatile("cp.async.wait_group 2;" ::: "memory");
        else if (kc == 6) asm volatile("cp.async.wait_group 1;" ::: "memory");
        else              asm volatile("cp.async.wait_group 0;" ::: "memory");
        __syncthreads();

        uint32_t bb = sbase + (kc % 3) * STAGE;
        #pragma unroll
        for (int ks = 0; ks < 4; ks++) {
            uint32_t ah[2][4], bh[4][4];
            #pragma unroll
            for (int mi = 0; mi < 2; mi++) {
                uint32_t ra = (uint32_t)((warpM * 32 + mi * 16 + (lane & 15)) * ROWB +
                                         ks * 32 + (lane >> 4) * 16);
                ldm4(ah[mi], bb + OFF_A + ra);
            }
            #pragma unroll
            for (int j = 0; j < 4; j++) {
                uint32_t rb = (uint32_t)((warpN * 64 + j * 16 + ((lane >> 4) << 3) + (lane & 7)) * ROWB +
                                         ks * 32 + ((lane >> 3) & 1) * 16);
                ldm4(bh[j], bb + OFF_B + rb);
            }
            #pragma unroll
            for (int mi = 0; mi < 2; mi++) {
                #pragma unroll
                for (int ni = 0; ni < 8; ni++) {
                    int j = ni >> 1, loc = ni & 1;
                    mma16816(acc[mi][ni], ah[mi], bh[j][loc * 2], bh[j][loc * 2 + 1]);
                }
            }
        }
        __syncthreads();
        int nx = kc + 3;
        if (nx < 8) { load_chunk(nx, nx % 3); CP_COMMIT(); }
    }

    // epilogue: apply norms, shifted sumexp + label capture
    int q = lane >> 2, qc = lane & 3;
    #pragma unroll
    for (int mi = 0; mi < 2; mi++) {
        #pragma unroll
        for (int half = 0; half < 2; half++) {
            int row = row0 + warpM * 32 + mi * 16 + half * 8 + q;
            float invA = SCALE_C * g_invRow[row];
            int lbl = labels[row & 255];
            float rs = 0.f;
            #pragma unroll
            for (int ni = 0; ni < 8; ni++) {
                #pragma unroll
                for (int j = 0; j < 2; j++) {
                    int c = col0 + warpN * 64 + ni * 8 + qc * 2 + j;
                    if (c < NCLS) {
                        float lg = acc[mi][ni][half * 2 + j] * invA * g_invW[c];
                        rs += __expf(lg - SCALE_C);
                        if (c == lbl) g_labelLogit[row] = lg;
                    }
                }
            }
            rs += __shfl_xor_sync(0xffffffffu, rs, 1);
            rs += __shfl_xor_sync(0xffffffffu, rs, 2);
            if (qc == 0) atomicAdd(&g_rowSumExp[row], rs);
        }
    }
}

// ================= mask loss (parallel stream) =================
__global__ __launch_bounds__(256) void k_mask(const float* __restrict__ seg,
                                              const int* __restrict__ masks) {
    __shared__ float sred[8];
    int n = blockIdx.x;
    int tid = threadIdx.x;
    const float4* base4 = (const float4*)(seg + (long long)n * NSEGC * NPIX);
    const int4* mb4 = (const int4*)(masks + n * NPIX);
    float lsum = 0.f;
    auto ce = [&](float a0, float a1, float a2, float a3, float a4, float a5, int k) {
        float m = fmaxf(fmaxf(fmaxf(a0, a1), fmaxf(a2, a3)), fmaxf(a4, a5));
        float s = __expf(a0 - m) + __expf(a1 - m) + __expf(a2 - m) +
                  __expf(a3 - m) + __expf(a4 - m) + __expf(a5 - m);
        float pk = k == 0 ? a0 : k == 1 ? a1 : k == 2 ? a2 : k == 3 ? a3 : k == 4 ? a4 : a5;
        lsum += m + __logf(s) - pk;
    };
    #pragma unroll
    for (int it = 0; it < 4; it++) {
        int pidx = tid + it * 256;
        float4 x[NSEGC];
        #pragma unroll
        for (int ch = 0; ch < NSEGC; ch++) x[ch] = base4[ch * 1024 + pidx];
        int4 kk = mb4[pidx];
        ce(x[0].x, x[1].x, x[2].x, x[3].x, x[4].x, x[5].x, kk.x);
        ce(x[0].y, x[1].y, x[2].y, x[3].y, x[4].y, x[5].y, kk.y);
        ce(x[0].z, x[1].z, x[2].z, x[3].z, x[4].z, x[5].z, kk.z);
        ce(x[0].w, x[1].w, x[2].w, x[3].w, x[4].w, x[5].w, kk.w);
    }
    float tot = blockReduceSum(lsum, sred);
    if (tid == 0) atomicAdd(&g_accum[0], tot);
}

// ================= sim GEMMs (z=0 global align fused; z=1..5 to scratch) =================
__global__ __launch_bounds__(256) void k_sim(
    const float* __restrict__ vis, const float* __restrict__ txt,
    const float* __restrict__ pe, const float* __restrict__ ae,
    const int* __restrict__ labels) {
    __shared__ float As[32][68];
    __shared__ float Bs[32][68];
    __shared__ float sred[8];
    int z = blockIdx.z;
    int tid = threadIdx.x;
    int tx = tid & 15, ty = tid >> 4;
    int r0 = blockIdx.y * 64, c0 = blockIdx.x * 64;

    const float* abase; const float* bbase; int aIdx, bIdx;
    if (z == 0) { abase = vis; bbase = txt; aIdx = 0; bIdx = 256; }
    else {
        int p = z - 1;
        abase = pe + p * 256 * DIMK; bbase = ae + p * 256 * DIMK;
        aIdx = 512 + p * 256; bIdx = 1792 + p * 256;
    }

    float acc[4][4];
    #pragma unroll
    for (int i = 0; i < 4; i++)
        #pragma unroll
        for (int j = 0; j < 4; j++) acc[i][j] = 0.f;

    int lm = tid >> 2, lseg = tid & 3;
    for (int kt = 0; kt < DIMK; kt += 32) {
        float4 v0 = *(const float4*)(abase + (r0 + lm) * DIMK + kt + lseg * 8);
        float4 v1 = *(const float4*)(abase + (r0 + lm) * DIMK + kt + lseg * 8 + 4);
        As[lseg * 8 + 0][lm] = v0.x; As[lseg * 8 + 1][lm] = v0.y;
        As[lseg * 8 + 2][lm] = v0.z; As[lseg * 8 + 3][lm] = v0.w;
        As[lseg * 8 + 4][lm] = v1.x; As[lseg * 8 + 5][lm] = v1.y;
        As[lseg * 8 + 6][lm] = v1.z; As[lseg * 8 + 7][lm] = v1.w;
        float4 w0 = *(const float4*)(bbase + (c0 + lm) * DIMK + kt + lseg * 8);
        float4 w1 = *(const float4*)(bbase + (c0 + lm) * DIMK + kt + lseg * 8 + 4);
        Bs[lseg * 8 + 0][lm] = w0.x; Bs[lseg * 8 + 1][lm] = w0.y;
        Bs[lseg * 8 + 2][lm] = w0.z; Bs[lseg * 8 + 3][lm] = w0.w;
        Bs[lseg * 8 + 4][lm] = w1.x; Bs[lseg * 8 + 5][lm] = w1.y;
        Bs[lseg * 8 + 6][lm] = w1.z; Bs[lseg * 8 + 7][lm] = w1.w;
        __syncthreads();
        #pragma unroll
        for (int k = 0; k < 32; k++) {
            float4 a = *(const float4*)&As[k][ty * 4];
            float4 bq = *(const float4*)&Bs[k][tx * 4];
            acc[0][0] = fmaf(a.x, bq.x, acc[0][0]); acc[0][1] = fmaf(a.x, bq.y, acc[0][1]);
            acc[0][2] = fmaf(a.x, bq.z, acc[0][2]); acc[0][3] = fmaf(a.x, bq.w, acc[0][3]);
            acc[1][0] = fmaf(a.y, bq.x, acc[1][0]); acc[1][1] = fmaf(a.y, bq.y, acc[1][1]);
            acc[1][2] = fmaf(a.y, bq.z, acc[1][2]); acc[1][3] = fmaf(a.y, bq.w, acc[1][3]);
            acc[2][0] = fmaf(a.z, bq.x, acc[2][0]); acc[2][1] = fmaf(a.z, bq.y, acc[2][1]);
            acc[2][2] = fmaf(a.z, bq.z, acc[2][2]); acc[2][3] = fmaf(a.z, bq.w, acc[2][3]);
            acc[3][0] = fmaf(a.w, bq.x, acc[3][0]); acc[3][1] = fmaf(a.w, bq.y, acc[3][1]);
            acc[3][2] = fmaf(a.w, bq.z, acc[3][2]); acc[3][3] = fmaf(a.w, bq.w, acc[3][3]);
        }
        __syncthreads();
    }

    if (z == 0) {
        float lsum = 0.f;
        #pragma unroll
        for (int ri = 0; ri < 4; ri++) {
            int r = r0 + ty * 4 + ri;
            int lr = labels[r];
            float ia = g_invRow[aIdx + r];
            #pragma unroll
            for (int ci = 0; ci < 4; ci++) {
                int c = c0 + tx * 4 + ci;
                float sv = acc[ri][ci] * ia * g_invRow[bIdx + c];
                lsum += (lr == labels[c]) ? softplusf(6.f - 10.f * sv)
                                          : softplusf(40.f * sv - 16.f);
            }
        }
        float tot = blockReduceSum(lsum, sred);
        if (tid == 0) atomicAdd(&g_accum[1], tot);
    } else {
        int p = z - 1;
        #pragma unroll
        for (int ri = 0; ri < 4; ri++) {
            int r = r0 + ty * 4 + ri;
            float ia = g_invRow[aIdx + r];
            #pragma unroll
            for (int ci = 0; ci < 4; ci++) {
                int c = c0 + tx * 4 + ci;
                g_sim[p * 65536 + r * 256 + c] = acc[ri][ci] * ia * g_invRow[bIdx + c];
            }
        }
    }
}

// ================= top-8 per row (z=0) / per column (z=1) =================
__global__ void k_top8() {
    int mode = blockIdx.z;
    int p = blockIdx.y;
    int w = threadIdx.x >> 5, lane = threadIdx.x & 31;
    int r = blockIdx.x * 8 + w;
    const float* base = g_sim + p * 65536;
    float v[8];
    #pragma unroll
    for (int j = 0; j < 8; j++) {
        int e = lane + j * 32;
        v[j] = mode ? base[e * 256 + r] : base[r * 256 + e];
    }
    int* out = (mode ? g_colTop : g_rowTop) + (p * 256 + r) * 8;
    for (int it = 0; it < 8; it++) {
        float bv = v[0]; int bj = 0;
        #pragma unroll
        for (int j = 1; j < 8; j++) if (v[j] > bv) { bv = v[j]; bj = j; }
        float mv = bv; int me = lane + bj * 32;
        #pragma unroll
        for (int o = 16; o; o >>= 1) {
            float ov = __shfl_xor_sync(0xffffffffu, mv, o);
            int oe = __shfl_xor_sync(0xffffffffu, me, o);
            if (ov > mv || (ov == mv && oe < me)) { mv = ov; me = oe; }
        }
        if (lane == 0) out[it] = me;
        if ((me & 31) == lane) v[me >> 5] = -__int_as_float(0x7f800000);
    }
}

// ================= local align with inline boost =================
__global__ void k_localb(const int* __restrict__ labels,
                         const int* __restrict__ vmask,
                         const int* __restrict__ tmask) {
    __shared__ unsigned char b1s[256];
    __shared__ int fwd2[8];
    __shared__ unsigned char hit2[8];
    __shared__ float sred[8];
    int p = blockIdx.y;
    int r = blockIdx.x;
    int tid = threadIdx.x;

    b1s[tid] = 0;
    __syncthreads();
    if (tid < 8) {
        int c = g_rowTop[(p * 256 + p) * 8 + tid];
        bool hit = false;
        #pragma unroll
        for (int m = 0; m < 8; m++) hit |= (g_colTop[(p * 256 + c) * 8 + m] == p);
        if (hit) b1s[c] = 1;
    } else if (tid < 16) {
        int k = tid - 8;
        int rr = g_colTop[(p * 256 + p) * 8 + k];
        bool hit = false;
        #pragma unroll
        for (int m = 0; m < 8; m++) hit |= (g_rowTop[(p * 256 + rr) * 8 + m] == p);
        fwd2[k] = rr;
        hit2[k] = hit ? 1 : 0;
    }
    __syncthreads();

    bool b2r = false;
    #pragma unroll
    for (int k = 0; k < 8; k++) b2r |= (fwd2[k] == r && hit2[k]);

    int c = tid;
    float s = g_sim[p * 65536 + r * 256 + c];
    bool match = labels[r] == labels[c];
    bool pm_r = vmask[r * NPART + p] != 0;
    bool pm_c = vmask[c * NPART + p] != 0;
    bool am_c = tmask[c * NPART + p] != 0;
    bool b1c = b1s[c] != 0;
    float Lp = softplusf(6.f - 10.f * s);
    float Ln = softplusf(40.f * s - 16.f);
    float v = 0.f;
    if (pm_r && am_c)          v += (match || b1c) ? Lp : Ln;   // b1 term
    if (pm_r && pm_c && am_c)  v += (match || b2r) ? Lp : Ln;   // b2 term (transposed)
    float tot = blockReduceSum(v, sred);
    if (tid == 0) atomicAdd(&g_accum[2], tot);
}

// ================= finalize =================
__global__ void k_final(float* __restrict__ out) {
    __shared__ float sred[512];
    int t = threadIdx.x;
    float v = logf(g_rowSumExp[t]) + SCALE_C - g_labelLogit[t];
    sred[t] = v;
    __syncthreads();
    for (int o = 256; o; o >>= 1) {
        if (t < o) sred[t] += sred[t + o];
        __syncthreads();
    }
    if (t == 0) {
        out[0] = sred[0] / 256.f;                                 // instance (v+t)
        out[1] = 5.f * g_accum[0] / (1280.f * 4096.f);            // mask
        out[2] = 2.f * g_accum[1] / 256.f;                        // global align
        out[3] = g_accum[2] / (5.f * 256.f);                      // local align
    }
}

// ---------------- launch: fork/join graph ----------------
extern "C" void kernel_launch(void* const* d_in, const int* in_sizes, int n_in,
                              void* d_out, int out_size) {
    const float* vis    = (const float*)d_in[0];
    const float* txt    = (const float*)d_in[1];
    const float* pe     = (const float*)d_in[2];
    const float* ae     = (const float*)d_in[3];
    const float* seg    = (const float*)d_in[4];
    const float* W      = (const float*)d_in[5];
    const int*   labels = (const int*)d_in[6];
    const int*   masks  = (const int*)d_in[7];
    const int*   vmask  = (const int*)d_in[8];
    const int*   tmask  = (const int*)d_in[9];
    float* out = (float*)d_out;

    static cudaStream_t sA = nullptr, sB = nullptr, sC = nullptr;
    static cudaEvent_t eRoot, ePrep, eMask, eNorm, eLocal;
    if (!sA) {
        cudaStreamCreateWithFlags(&sA, cudaStreamNonBlocking);
        cudaStreamCreateWithFlags(&sB, cudaStreamNonBlocking);
        cudaStreamCreateWithFlags(&sC, cudaStreamNonBlocking);
        cudaEventCreateWithFlags(&eRoot, cudaEventDisableTiming);
        cudaEventCreateWithFlags(&ePrep, cudaEventDisableTiming);
        cudaEventCreateWithFlags(&eMask, cudaEventDisableTiming);
        cudaEventCreateWithFlags(&eNorm, cudaEventDisableTiming);
        cudaEventCreateWithFlags(&eLocal, cudaEventDisableTiming);
        cudaFuncSetAttribute(k_mma, cudaFuncAttributeMaxDynamicSharedMemorySize, SM_TOTAL);
    }

    // root
    k_init0<<<1, 512>>>();
    cudaEventRecord(eRoot, 0);

    // branch A: fused prep (A convert + W colnorm+transpose single pass)
    cudaStreamWaitEvent(sA, eRoot, 0);
    k_prepAW<<<NB_PREPA + NB_PREPW, 256, 0, sA>>>(vis, txt, W);
    cudaEventRecord(ePrep, sA);

    // branch B: mask loss (independent)
    cudaStreamWaitEvent(sB, eRoot, 0);
    k_mask<<<1280, 256, 0, sB>>>(seg, masks);
    cudaEventRecord(eMask, sB);

    // main stream: row norms
    k_pre1<<<NB_ROWNORM, 256>>>(vis, txt, pe, ae);
    cudaEventRecord(eNorm, 0);

    // branch C: sim -> top8 -> localb (needs row norms)
    cudaStreamWaitEvent(sC, eNorm, 0);
    k_sim<<<dim3(4, 4, 6), 256, 0, sC>>>(vis, txt, pe, ae, labels);
    k_top8<<<dim3(32, NPART, 2), 256, 0, sC>>>();
    k_localb<<<dim3(256, NPART), 256, 0, sC>>>(labels, vmask, tmask);
    cudaEventRecord(eLocal, sC);

    // main stream: mma (needs prep + row norms), then join + finalize
    cudaStreamWaitEvent(0, ePrep, 0);
    k_mma<<<NB_MMA, 256, SM_TOTAL>>>(labels);
    cudaStreamWaitEvent(0, eMask, 0);
    cudaStreamWaitEvent(0, eLocal, 0);
    k_final<<<1, 512>>>(out);
}